// round 1
// baseline (speedup 1.0000x reference)
#include <cuda_runtime.h>
#include <math.h>
#include <stdint.h>

// ---------------- problem dims ----------------
#define Bq   4096
#define Tt   31
#define Cc   768
#define BDq  128
#define AUGq 384
#define NUq  256     // lin0 out
#define HHq  64      // lstm hidden
#define NGq  512     // gates both directions (4H * 2)
#define OOq  12
#define TWq  11      // attention window length (t in [10,21))
#define BTq  (Bq*Tt) // 126976

// ---------------- device scratch (no allocations allowed) ----------------
static __device__ float g_xs  [(size_t)Bq*Tt*Cc];    // x_smooth
static __device__ float g_xbar[(size_t)Bq*Cc];       // window mean of x_smooth
static __device__ float g_P   [(size_t)Bq*Tt*AUGq];  // xs @ [cls|delta|acc]
static __device__ float g_v   [(size_t)Bq*Tt*AUGq];  // x_aug (post gelu+LN)
static __device__ float g_u   [(size_t)Bq*Tt*NUq];   // gelu(lin0)
static __device__ float g_ubar[(size_t)Bq*NUq];      // time-mean of u
static __device__ float g_G   [(size_t)Bq*Tt*NGq];   // u @ [wih_f|wih_r]
static __device__ float g_gbar[(size_t)Bq*NGq];      // ubar @ [wih_f|wih_r]
static __device__ float g_W3  [(size_t)Cc*AUGq];     // packed cls|delta|acc weights
static __device__ float g_Wih [(size_t)NUq*NGq];     // packed wih_f|wih_r
static __device__ float g_winf[(size_t)Bq*TWq*HHq];  // fwd hidden states in window
static __device__ float g_winb[(size_t)Bq*TWq*HHq];  // bwd hidden states in window
static __device__ float g_linlog[(size_t)Bq*OOq];

// ---------------- helpers ----------------
__device__ __forceinline__ float geluf(float x) {
    return 0.5f * x * (1.0f + erff(x * 0.7071067811865476f));
}
__device__ __forceinline__ float sigf(float x) { return 1.0f / (1.0f + expf(-x)); }

__device__ __forceinline__ unsigned long long pk2(float lo, float hi) {
    unsigned long long r;
    asm("mov.b64 %0, {%1, %2};" : "=l"(r) : "f"(lo), "f"(hi));
    return r;
}
__device__ __forceinline__ void upk2(unsigned long long v, float& lo, float& hi) {
    asm("mov.b64 {%0, %1}, %2;" : "=f"(lo), "=f"(hi) : "l"(v));
}
#define FMA2(acc, a, b) asm("fma.rn.f32x2 %0, %1, %2, %0;" : "+l"(acc) : "l"(a), "l"(b))

// block-wide sum over 128 threads; all threads receive the result
__device__ __forceinline__ float blksum128(float v, volatile float* sw) {
    #pragma unroll
    for (int o = 16; o > 0; o >>= 1) v += __shfl_down_sync(0xffffffffu, v, o);
    int lane = threadIdx.x & 31, w = threadIdx.x >> 5;
    __syncthreads();                 // protect previous use of sw
    if (lane == 0) sw[w] = v;
    __syncthreads();
    return sw[0] + sw[1] + sw[2] + sw[3];
}

// ---------------- pack weights ----------------
__global__ void pack_kernel(const float* __restrict__ cls_w, const float* __restrict__ delta_w,
                            const float* __restrict__ acc_w, const float* __restrict__ wih_f,
                            const float* __restrict__ wih_r) {
    int idx = blockIdx.x * blockDim.x + threadIdx.x;
    if (idx < Cc * AUGq) {
        int c = idx / AUGq, n = idx % AUGq;
        float v;
        if (n < BDq)           v = cls_w[c * BDq + n];
        else if (n < 2 * BDq)  v = delta_w[c * BDq + (n - BDq)];
        else                   v = acc_w[c * BDq + (n - 2 * BDq)];
        g_W3[idx] = v;
    }
    if (idx < NUq * NGq) {
        int c = idx / NGq, n = idx % NGq;
        g_Wih[idx] = (n < 256) ? wih_f[c * 256 + n] : wih_r[c * 256 + (n - 256)];
    }
}

// ---------------- EMA scan + window mean ----------------
__global__ void ema_kernel(const float* __restrict__ x) {
    int idx = blockIdx.x * blockDim.x + threadIdx.x;
    if (idx >= Bq * Cc) return;
    int b = idx / Cc, c = idx % Cc;
    const float* xp = x + (size_t)b * Tt * Cc + c;
    float* xsp = g_xs + (size_t)b * Tt * Cc + c;
    float s = xp[0];
    xsp[0] = s;
    float wsum = 0.0f;
    #pragma unroll
    for (int t = 1; t < Tt; t++) {
        float xt = xp[(size_t)t * Cc];
        s = s + 0.3f * (xt - s);
        xsp[(size_t)t * Cc] = s;
        if (t >= 10 && t < 21) wsum += s;
    }
    g_xbar[idx] = wsum * (1.0f / 11.0f);
}

// ---------------- SGEMM 128x128x8, f32x2 packed FMA ----------------
// A: MxK row-major, B: KxN row-major, C: MxN. M%128==0, N%128==0, K%8==0.
// EPI==0: raw store. EPI==1: C = gelu(acc + bias[n]).
template <int EPI>
__global__ __launch_bounds__(256) void sgemm_k(const float* __restrict__ A,
                                               const float* __restrict__ Bm,
                                               float* __restrict__ Cm,
                                               int M, int N, int K,
                                               const float* __restrict__ bias) {
    __shared__ float As[8][128];
    __shared__ float Bs[8][128];
    const int tid = threadIdx.x;
    const int tx = tid & 15, ty = tid >> 4;         // 16x16 thread grid
    const int bm = blockIdx.y << 7, bn = blockIdx.x << 7;
    const int arow = tid >> 1, acol = (tid & 1) << 2;
    const int brow = tid >> 5, bcol = (tid & 31) << 2;

    unsigned long long acc[8][4];
    #pragma unroll
    for (int m = 0; m < 8; m++)
        #pragma unroll
        for (int p = 0; p < 4; p++) acc[m][p] = 0ull;

    const float* Ap = A + (size_t)(bm + arow) * K + acol;
    const float* Bp = Bm + (size_t)brow * N + bn + bcol;

    for (int k0 = 0; k0 < K; k0 += 8) {
        float4 av = *reinterpret_cast<const float4*>(Ap + k0);
        As[acol + 0][arow] = av.x;
        As[acol + 1][arow] = av.y;
        As[acol + 2][arow] = av.z;
        As[acol + 3][arow] = av.w;
        float4 bv = *reinterpret_cast<const float4*>(Bp + (size_t)k0 * N);
        *reinterpret_cast<float4*>(&Bs[brow][bcol]) = bv;
        __syncthreads();
        #pragma unroll
        for (int kk = 0; kk < 8; kk++) {
            float4 a0 = *reinterpret_cast<const float4*>(&As[kk][ty << 3]);
            float4 a1 = *reinterpret_cast<const float4*>(&As[kk][(ty << 3) + 4]);
            unsigned long long ap[8];
            ap[0] = pk2(a0.x, a0.x); ap[1] = pk2(a0.y, a0.y);
            ap[2] = pk2(a0.z, a0.z); ap[3] = pk2(a0.w, a0.w);
            ap[4] = pk2(a1.x, a1.x); ap[5] = pk2(a1.y, a1.y);
            ap[6] = pk2(a1.z, a1.z); ap[7] = pk2(a1.w, a1.w);
            unsigned long long bp[4];
            #pragma unroll
            for (int p = 0; p < 4; p++)
                bp[p] = *reinterpret_cast<const unsigned long long*>(&Bs[kk][(tx << 3) + (p << 1)]);
            #pragma unroll
            for (int m = 0; m < 8; m++)
                #pragma unroll
                for (int p = 0; p < 4; p++) FMA2(acc[m][p], ap[m], bp[p]);
        }
        __syncthreads();
    }

    #pragma unroll
    for (int m = 0; m < 8; m++) {
        size_t grow = (size_t)(bm + (ty << 3) + m) * N + bn + (tx << 3);
        #pragma unroll
        for (int p = 0; p < 4; p++) {
            float lo, hi;
            upk2(acc[m][p], lo, hi);
            if (EPI == 1) {
                int gn = bn + (tx << 3) + (p << 1);
                lo = geluf(lo + bias[gn]);
                hi = geluf(hi + bias[gn + 1]);
            }
            float2 st; st.x = lo; st.y = hi;
            *reinterpret_cast<float2*>(&Cm[grow + (p << 1)]) = st;
        }
    }
}

// ---------------- streams: P -> gelu -> LN -> x_aug (g_v) ----------------
__global__ __launch_bounds__(128) void streams_kernel(
    const float* __restrict__ cls_b, const float* __restrict__ delta_b,
    const float* __restrict__ acc_b,
    const float* __restrict__ cg, const float* __restrict__ cbb,
    const float* __restrict__ dg, const float* __restrict__ dbb,
    const float* __restrict__ ag, const float* __restrict__ abb) {
    __shared__ float red[4];
    int row = blockIdx.x;                 // b*T + t
    int t = row % Tt;
    int j = threadIdx.x;                  // 0..127
    const float* Pr = g_P + (size_t)row * AUGq;
    float* vr = g_v + (size_t)row * AUGq;

    float pre[3];
    pre[0] = Pr[j] + cls_b[j];
    {   // delta_stream[t] = xs[t]-xs[t-1] (t>=1); t==0: xs[0]-xs[1]
        int o = BDq + j;
        float d = (t == 0) ? (Pr[o] - Pr[AUGq + o]) : (Pr[o] - Pr[o - AUGq]);
        pre[1] = d + delta_b[j];
    }
    {   // acc_stream: t>=2: x[t]-2x[t-1]+x[t-2]; t==1: 2x[1]-2x[0]; t==0: x[0]-2x[1]+x[2]
        int o = 2 * BDq + j;
        float a;
        if (t == 0)      a = Pr[o] - 2.0f * Pr[AUGq + o] + Pr[2 * AUGq + o];
        else if (t == 1) a = 2.0f * Pr[o] - 2.0f * Pr[o - AUGq];
        else             a = Pr[o] - 2.0f * Pr[o - AUGq] + Pr[o - 2 * AUGq];
        pre[2] = a + acc_b[j];
    }
    #pragma unroll
    for (int s = 0; s < 3; s++) {
        float aact = geluf(pre[s]);
        float mu = blksum128(aact, red) * (1.0f / 128.0f);
        float dd = aact - mu;
        float var = blksum128(dd * dd, red) * (1.0f / 128.0f);
        const float* gp  = (s == 0) ? cg  : (s == 1) ? dg  : ag;
        const float* bp2 = (s == 0) ? cbb : (s == 1) ? dbb : abb;
        vr[s * BDq + j] = dd * rsqrtf(var + 1e-5f) * gp[j] + bp2[j];
    }
}

// ---------------- time-mean of u ----------------
__global__ void ubar_kernel() {
    int idx = blockIdx.x * blockDim.x + threadIdx.x;
    if (idx >= Bq * NUq) return;
    int b = idx / NUq, n = idx % NUq;
    const float* up = g_u + (size_t)b * Tt * NUq + n;
    float s = 0.0f;
    #pragma unroll
    for (int t = 0; t < Tt; t++) s += up[(size_t)t * NUq];
    g_ubar[idx] = s * (1.0f / 31.0f);
}

// ---------------- BiLSTM (batch-parallel recurrence) ----------------
#define RPB 8
__global__ __launch_bounds__(256) void lstm_kernel(const float* __restrict__ whh_f,
                                                   const float* __restrict__ b_f,
                                                   const float* __restrict__ whh_r,
                                                   const float* __restrict__ b_r) {
    const int dir = blockIdx.y;               // 0 fwd, 1 bwd
    const int b0 = blockIdx.x * RPB;
    const int j = threadIdx.x;                // gate column 0..255
    const float* whh  = dir ? whh_r : whh_f;
    const float* bias = dir ? b_r : b_f;
    const int off = dir ? 256 : 0;
    float* winbuf = dir ? g_winb : g_winf;

    float wcol[64];
    #pragma unroll
    for (int kk = 0; kk < 64; kk++) wcol[kk] = whh[kk * 256 + j];
    float base[RPB];
    #pragma unroll
    for (int r = 0; r < RPB; r++)
        base[r] = bias[j] - g_gbar[(size_t)(b0 + r) * NGq + off + j];

    __shared__ float hs[RPB][64];
    __shared__ float gs[RPB][256];
    if (j < 64) {
        #pragma unroll
        for (int r = 0; r < RPB; r++) hs[r][j] = 0.0f;
    }
    float creg[RPB];
    #pragma unroll
    for (int r = 0; r < RPB; r++) creg[r] = 0.0f;
    __syncthreads();

    for (int s = 0; s < Tt; s++) {
        int t = dir ? (Tt - 1 - s) : s;
        #pragma unroll
        for (int r = 0; r < RPB; r++) {
            float g = base[r] + g_G[((size_t)(b0 + r) * Tt + t) * NGq + off + j];
            #pragma unroll
            for (int kk = 0; kk < 64; kk += 4) {
                float4 h4 = *reinterpret_cast<const float4*>(&hs[r][kk]);
                g += wcol[kk] * h4.x + wcol[kk + 1] * h4.y
                   + wcol[kk + 2] * h4.z + wcol[kk + 3] * h4.w;
            }
            gs[r][j] = g;
        }
        __syncthreads();
        if (j < 64) {
            #pragma unroll
            for (int r = 0; r < RPB; r++) {
                float ig = sigf(gs[r][j]);
                float fg = sigf(gs[r][64 + j]);
                float gg = tanhf(gs[r][128 + j]);
                float og = sigf(gs[r][192 + j]);
                float c = fg * creg[r] + ig * gg;
                creg[r] = c;
                float h = og * tanhf(c);
                hs[r][j] = h;
                if (s >= 10 && s <= 20) {
                    int wt = dir ? (20 - s) : (s - 10);
                    winbuf[((size_t)(b0 + r) * TWq + wt) * HHq + j] = h;
                }
            }
        }
        __syncthreads();
    }
}

// ---------------- linear logits (xbar @ lin1_w + b) ----------------
__global__ void linlog_kernel(const float* __restrict__ w, const float* __restrict__ bb) {
    int idx = blockIdx.x * blockDim.x + threadIdx.x;
    if (idx >= Bq * OOq) return;
    int b = idx / OOq, o = idx % OOq;
    const float* xb = g_xbar + (size_t)b * Cc;
    float s = bb[o];
    #pragma unroll 8
    for (int c = 0; c < Cc; c++) s += xb[c] * w[c * OOq + o];
    g_linlog[idx] = s;
}

// ---------------- attention + final gate ----------------
__global__ __launch_bounds__(128) void attn_final_kernel(
    const float* __restrict__ attn_w, const float* __restrict__ attn_b,
    const float* __restrict__ attn_temp, const float* __restrict__ lin2_w,
    const float* __restrict__ lin2_b, const float* __restrict__ gate,
    float* __restrict__ out) {
    __shared__ float red[4];
    __shared__ float att[128];
    int b = blockIdx.x, k = threadIdx.x;
    float win[TWq];
    const float* src = (k < HHq) ? (g_winf + (size_t)b * TWq * HHq + k)
                                 : (g_winb + (size_t)b * TWq * HHq + (k - HHq));
    #pragma unroll
    for (int t = 0; t < TWq; t++) win[t] = src[t * HHq];

    float aw = attn_w[k];
    float ab = attn_b[0];
    float temp = log1pf(expf(attn_temp[0])) + 0.001f;
    float sc[TWq];
    #pragma unroll
    for (int t = 0; t < TWq; t++)
        sc[t] = (blksum128(win[t] * aw, red) + ab) / temp;

    float mx = sc[0];
    #pragma unroll
    for (int t = 1; t < TWq; t++) mx = fmaxf(mx, sc[t]);
    float den = 0.0f;
    #pragma unroll
    for (int t = 0; t < TWq; t++) { sc[t] = expf(sc[t] - mx); den += sc[t]; }
    float inv = 1.0f / den;
    float at = 0.0f;
    #pragma unroll
    for (int t = 0; t < TWq; t++) at += sc[t] * inv * win[t];

    out[(size_t)Bq * OOq + (size_t)b * 128 + k] = at;   // attended
    att[k] = at;
    __syncthreads();
    if (k < OOq) {
        float s = lin2_b[k];
        #pragma unroll 8
        for (int kk = 0; kk < 128; kk++) s += att[kk] * lin2_w[kk * OOq + k];
        float lin = g_linlog[b * OOq + k];
        float gg = 1.0f / (1.0f + expf(-gate[0]));
        out[b * OOq + k] = lin + gg * (s - lin);        // final_logits
    }
}

// ---------------- launch ----------------
extern "C" void kernel_launch(void* const* d_in, const int* in_sizes, int n_in,
                              void* d_out, int out_size) {
    const float* x        = (const float*)d_in[0];
    const float* cls_w    = (const float*)d_in[1];
    const float* cls_b    = (const float*)d_in[2];
    const float* delta_w  = (const float*)d_in[3];
    const float* delta_b  = (const float*)d_in[4];
    const float* acc_w    = (const float*)d_in[5];
    const float* acc_b    = (const float*)d_in[6];
    const float* cls_ln_g = (const float*)d_in[7];
    const float* cls_ln_b = (const float*)d_in[8];
    const float* delta_ln_g = (const float*)d_in[9];
    const float* delta_ln_b = (const float*)d_in[10];
    const float* acc_ln_g = (const float*)d_in[11];
    const float* acc_ln_b = (const float*)d_in[12];
    const float* lin0_w   = (const float*)d_in[13];
    const float* lin0_b   = (const float*)d_in[14];
    const float* gate     = (const float*)d_in[15];
    const float* attn_w   = (const float*)d_in[16];
    const float* attn_b   = (const float*)d_in[17];
    const float* attn_temp= (const float*)d_in[18];
    const float* lin1_w   = (const float*)d_in[19];
    const float* lin1_b   = (const float*)d_in[20];
    const float* lin2_w   = (const float*)d_in[21];
    const float* lin2_b   = (const float*)d_in[22];
    const float* wih_f    = (const float*)d_in[23];
    const float* whh_f    = (const float*)d_in[24];
    const float* b_f      = (const float*)d_in[25];
    const float* wih_r    = (const float*)d_in[26];
    const float* whh_r    = (const float*)d_in[27];
    const float* b_r      = (const float*)d_in[28];
    float* out = (float*)d_out;

    float *p_xs, *p_P, *p_v, *p_u, *p_ubar, *p_G, *p_gbar, *p_W3, *p_Wih;
    cudaGetSymbolAddress((void**)&p_xs,   g_xs);
    cudaGetSymbolAddress((void**)&p_P,    g_P);
    cudaGetSymbolAddress((void**)&p_v,    g_v);
    cudaGetSymbolAddress((void**)&p_u,    g_u);
    cudaGetSymbolAddress((void**)&p_ubar, g_ubar);
    cudaGetSymbolAddress((void**)&p_G,    g_G);
    cudaGetSymbolAddress((void**)&p_gbar, g_gbar);
    cudaGetSymbolAddress((void**)&p_W3,   g_W3);
    cudaGetSymbolAddress((void**)&p_Wih,  g_Wih);

    // 1. pack weights
    pack_kernel<<<(Cc * AUGq + 255) / 256, 256>>>(cls_w, delta_w, acc_w, wih_f, wih_r);
    // 2. EMA scan + window mean
    ema_kernel<<<(Bq * Cc + 255) / 256, 256>>>(x);
    // 3. P = xs @ W3   (126976 x 768 x 384)
    sgemm_k<0><<<dim3(AUGq / 128, BTq / 128), 256>>>(p_xs, p_W3, p_P, BTq, AUGq, Cc, nullptr);
    // 4. streams -> gelu -> LN -> x_aug
    streams_kernel<<<BTq, 128>>>(cls_b, delta_b, acc_b,
                                 cls_ln_g, cls_ln_b, delta_ln_g, delta_ln_b,
                                 acc_ln_g, acc_ln_b);
    // 5. u = gelu(v @ lin0_w + b)   (126976 x 384 x 256)
    sgemm_k<1><<<dim3(NUq / 128, BTq / 128), 256>>>(p_v, lin0_w, p_u, BTq, NUq, AUGq, lin0_b);
    // 6. ubar = mean_t(u)
    ubar_kernel<<<(Bq * NUq + 255) / 256, 256>>>();
    // 7. G = u @ Wih   (126976 x 256 x 512)
    sgemm_k<0><<<dim3(NGq / 128, BTq / 128), 256>>>(p_u, p_Wih, p_G, BTq, NGq, NUq, nullptr);
    // 8. gbar = ubar @ Wih   (4096 x 256 x 512)
    sgemm_k<0><<<dim3(NGq / 128, Bq / 128), 256>>>(p_ubar, p_Wih, p_gbar, Bq, NGq, NUq, nullptr);
    // 9. BiLSTM recurrence
    lstm_kernel<<<dim3(Bq / RPB, 2), 256>>>(whh_f, b_f, whh_r, b_r);
    // 10. linear logits
    linlog_kernel<<<(Bq * OOq + 255) / 256, 256>>>(lin1_w, lin1_b);
    // 11. attention + final mix -> out
    attn_final_kernel<<<Bq, 128>>>(attn_w, attn_b, attn_temp, lin2_w, lin2_b, gate, out);
}

// round 7
// speedup vs baseline: 1.7622x; 1.7622x over previous
#include <cuda_runtime.h>
#include <cuda_bf16.h>
#include <math.h>
#include <stdint.h>

// ---------------- problem dims ----------------
#define Bq   4096
#define Tt   31
#define Cc   768
#define BDq  128
#define AUGq 384
#define NUq  256     // lin0 out
#define HHq  64      // lstm hidden
#define NGq  512     // gates both directions (4H * 2)
#define OOq  12
#define TWq  11      // attention window length (t in [10,21))
#define BTq  (Bq*Tt) // 126976

// ---------------- device scratch (no allocations allowed) ----------------
static __device__ float g_xs  [(size_t)Bq*Tt*Cc];    // x_smooth
static __device__ float g_xbar[(size_t)Bq*Cc];       // window mean of x_smooth
static __device__ float g_P   [(size_t)Bq*Tt*AUGq];  // xs @ [cls|delta|acc]
static __device__ float g_v   [(size_t)Bq*Tt*AUGq];  // x_aug (post gelu+LN)
static __device__ float g_u   [(size_t)Bq*Tt*NUq];   // gelu(lin0)
static __device__ float g_ubar[(size_t)Bq*NUq];      // time-mean of u
static __device__ float g_G   [(size_t)Bq*Tt*NGq];   // u @ [wih_f|wih_r]
static __device__ float g_gbar[(size_t)Bq*NGq];      // ubar @ [wih_f|wih_r]
static __device__ float g_winf[(size_t)Bq*TWq*HHq];  // fwd hidden states in window
static __device__ float g_winb[(size_t)Bq*TWq*HHq];  // bwd hidden states in window
static __device__ float g_linlog[(size_t)Bq*OOq];

// bf16 split weight matrices, stored [N][K] (K-major, i.e. transposed)
static __device__ __nv_bfloat16 g_W3t_hi[(size_t)AUGq*Cc],  g_W3t_lo[(size_t)AUGq*Cc];
static __device__ __nv_bfloat16 g_L0t_hi[(size_t)NUq*AUGq], g_L0t_lo[(size_t)NUq*AUGq];
static __device__ __nv_bfloat16 g_Wt_hi [(size_t)NGq*NUq],  g_Wt_lo [(size_t)NGq*NUq];

// ---------------- generic helpers ----------------
__device__ __forceinline__ float geluf(float x) {
    return 0.5f * x * (1.0f + erff(x * 0.7071067811865476f));
}
__device__ __forceinline__ float sigf(float x) { return 1.0f / (1.0f + expf(-x)); }

// block-wide sum over 128 threads; all threads receive the result
__device__ __forceinline__ float blksum128(float v, volatile float* sw) {
    #pragma unroll
    for (int o = 16; o > 0; o >>= 1) v += __shfl_down_sync(0xffffffffu, v, o);
    int lane = threadIdx.x & 31, w = threadIdx.x >> 5;
    __syncthreads();
    if (lane == 0) sw[w] = v;
    __syncthreads();
    return sw[0] + sw[1] + sw[2] + sw[3];
}

// split a float into bf16 hi + bf16 lo (residual)
__device__ __forceinline__ void split1(float x, __nv_bfloat16& h, __nv_bfloat16& l) {
    h = __float2bfloat16(x);
    l = __float2bfloat16(x - __bfloat162float(h));
}

__device__ __forceinline__ void split4(float4 v, unsigned long long& hv, unsigned long long& lv) {
    __nv_bfloat16 h0, h1, h2, h3, l0, l1, l2, l3;
    split1(v.x, h0, l0); split1(v.y, h1, l1);
    split1(v.z, h2, l2); split1(v.w, h3, l3);
    hv = (unsigned long long)__bfloat16_as_ushort(h0)
       | ((unsigned long long)__bfloat16_as_ushort(h1) << 16)
       | ((unsigned long long)__bfloat16_as_ushort(h2) << 32)
       | ((unsigned long long)__bfloat16_as_ushort(h3) << 48);
    lv = (unsigned long long)__bfloat16_as_ushort(l0)
       | ((unsigned long long)__bfloat16_as_ushort(l1) << 16)
       | ((unsigned long long)__bfloat16_as_ushort(l2) << 32)
       | ((unsigned long long)__bfloat16_as_ushort(l3) << 48);
}

// mma.sync m16n8k16 bf16 -> f32 accumulate (HMMA path; target-generic PTX)
__device__ __forceinline__ void mma16816(float* c, const uint32_t* a, const uint32_t* b) {
    asm volatile(
        "mma.sync.aligned.m16n8k16.row.col.f32.bf16.bf16.f32 "
        "{%0,%1,%2,%3}, {%4,%5,%6,%7}, {%8,%9}, {%0,%1,%2,%3};"
        : "+f"(c[0]), "+f"(c[1]), "+f"(c[2]), "+f"(c[3])
        : "r"(a[0]), "r"(a[1]), "r"(a[2]), "r"(a[3]), "r"(b[0]), "r"(b[1]));
}

// ---------------- weight convert: pack + transpose + bf16 split ----------------
__global__ void convert_b_kernel(const float* __restrict__ cls_w, const float* __restrict__ delta_w,
                                 const float* __restrict__ acc_w, const float* __restrict__ lin0_w,
                                 const float* __restrict__ wih_f, const float* __restrict__ wih_r) {
    int idx = blockIdx.x * blockDim.x + threadIdx.x;
    if (idx < AUGq * Cc) {
        int n = idx / Cc, c = idx % Cc;
        float w = (n < BDq) ? cls_w[c * BDq + n]
                : (n < 2 * BDq) ? delta_w[c * BDq + (n - BDq)]
                : acc_w[c * BDq + (n - 2 * BDq)];
        split1(w, g_W3t_hi[idx], g_W3t_lo[idx]);
    }
    if (idx < NUq * AUGq) {
        int n = idx / AUGq, c = idx % AUGq;
        split1(lin0_w[c * NUq + n], g_L0t_hi[idx], g_L0t_lo[idx]);
    }
    if (idx < NGq * NUq) {
        int n = idx >> 8, c = idx & 255;
        float w = (n < 256) ? wih_f[c * 256 + n] : wih_r[c * 256 + (n - 256)];
        split1(w, g_Wt_hi[idx], g_Wt_lo[idx]);
    }
}

// ---------------- EMA scan + window mean ----------------
__global__ void ema_kernel(const float* __restrict__ x) {
    int idx = blockIdx.x * blockDim.x + threadIdx.x;
    if (idx >= Bq * Cc) return;
    int b = idx / Cc, c = idx % Cc;
    const float* xp = x + (size_t)b * Tt * Cc + c;
    float* xsp = g_xs + (size_t)b * Tt * Cc + c;
    float s = xp[0];
    xsp[0] = s;
    float wsum = 0.0f;
    #pragma unroll
    for (int t = 1; t < Tt; t++) {
        float xt = xp[(size_t)t * Cc];
        s = s + 0.3f * (xt - s);
        xsp[(size_t)t * Cc] = s;
        if (t >= 10 && t < 21) wsum += s;
    }
    g_xbar[idx] = wsum * (1.0f / 11.0f);
}

// ---------------- HMMA GEMM: C[M,N] = A[M,K](fp32) @ Bt[N,K](bf16 hi+lo)^T -------------
// 128x128 block tile, BK=32, 8 warps (warp tile 32x64), double-buffered SMEM,
// register prefetch, split-bf16 (Ah*Bh + Ah*Bl + Al*Bh).
// SMEM rows: 40 halves (80B) stride -> conflict-free fragment LDS + 16B-aligned STS.
// EPI==0: raw store. EPI==1: gelu(acc + bias[n]).
#define G_STRIDE 80                   // bytes per smem row
#define G_MAT    (128 * G_STRIDE)     // 10240 bytes per matrix
#define G_STAGE  (4 * G_MAT)          // Ah, Al, Bh, Bl
#define G_SMEM   (2 * G_STAGE)        // 81920 bytes

template<int EPI>
__global__ __launch_bounds__(256, 1)
void gemm_hmma(const float* __restrict__ A, const __nv_bfloat16* __restrict__ Bhg,
               const __nv_bfloat16* __restrict__ Blg, float* __restrict__ Cm,
               int M, int N, int K, const float* __restrict__ bias) {
    extern __shared__ char smem[];
    const int tid = threadIdx.x, wid = tid >> 5, lane = tid & 31;
    const int grp = lane >> 2, tig = lane & 3;
    const int m0 = blockIdx.y << 7, n0 = blockIdx.x << 7;
    const int warpM = (wid >> 1) << 5, warpN = (wid & 1) << 6;

    float acc[2][8][4];
    #pragma unroll
    for (int mi = 0; mi < 2; mi++)
        #pragma unroll
        for (int ni = 0; ni < 8; ni++)
            #pragma unroll
            for (int q = 0; q < 4; q++) acc[mi][ni][q] = 0.0f;

    const int nc = K >> 5;

    float4 av[4];
    uint4  bhv[2], blv[2];

    // ---- load chunk c into registers ----
    auto ldg = [&](int c) {
        const int k0 = c << 5;
        #pragma unroll
        for (int i = 0; i < 4; i++) {
            int id = (i << 8) + tid;            // 0..1023
            int r = id >> 3, c4 = id & 7;       // 8 float4 per A row
            av[i] = *reinterpret_cast<const float4*>(A + (size_t)(m0 + r) * K + k0 + (c4 << 2));
        }
        #pragma unroll
        for (int i = 0; i < 2; i++) {
            int id = (i << 8) + tid;            // 0..511
            int r = id >> 2, c16 = id & 3;      // 4 x 16B per B row
            size_t go = (size_t)(n0 + r) * K + k0 + (c16 << 3);
            bhv[i] = *reinterpret_cast<const uint4*>(Bhg + go);
            blv[i] = *reinterpret_cast<const uint4*>(Blg + go);
        }
    };
    // ---- store registers into smem stage s (with A fp32->bf16 split) ----
    auto sts = [&](int s) {
        char* st = smem + s * G_STAGE;
        #pragma unroll
        for (int i = 0; i < 4; i++) {
            int id = (i << 8) + tid;
            int r = id >> 3, c4 = id & 7;
            unsigned long long hv, lv;
            split4(av[i], hv, lv);
            *reinterpret_cast<unsigned long long*>(st + r * G_STRIDE + (c4 << 3)) = hv;           // Ah
            *reinterpret_cast<unsigned long long*>(st + G_MAT + r * G_STRIDE + (c4 << 3)) = lv;   // Al
        }
        #pragma unroll
        for (int i = 0; i < 2; i++) {
            int id = (i << 8) + tid;
            int r = id >> 2, c16 = id & 3;
            *reinterpret_cast<uint4*>(st + 2 * G_MAT + r * G_STRIDE + (c16 << 4)) = bhv[i];       // Bh
            *reinterpret_cast<uint4*>(st + 3 * G_MAT + r * G_STRIDE + (c16 << 4)) = blv[i];       // Bl
        }
    };
    // ---- compute on smem stage s ----
    auto compute = [&](int s) {
        const char* st = smem + s * G_STAGE;
        #pragma unroll
        for (int ks = 0; ks < 2; ks++) {
            const int kb = ks << 4;             // k offset in halves
            uint32_t ah[2][4], al[2][4];
            #pragma unroll
            for (int mi = 0; mi < 2; mi++) {
                const char* ba = st + (warpM + (mi << 4) + grp) * G_STRIDE;
                int co0 = (kb + (tig << 1)) << 1;        // byte offset
                int co1 = (kb + (tig << 1) + 8) << 1;
                ah[mi][0] = *reinterpret_cast<const uint32_t*>(ba + co0);
                ah[mi][1] = *reinterpret_cast<const uint32_t*>(ba + 8 * G_STRIDE + co0);
                ah[mi][2] = *reinterpret_cast<const uint32_t*>(ba + co1);
                ah[mi][3] = *reinterpret_cast<const uint32_t*>(ba + 8 * G_STRIDE + co1);
                al[mi][0] = *reinterpret_cast<const uint32_t*>(ba + G_MAT + co0);
                al[mi][1] = *reinterpret_cast<const uint32_t*>(ba + G_MAT + 8 * G_STRIDE + co0);
                al[mi][2] = *reinterpret_cast<const uint32_t*>(ba + G_MAT + co1);
                al[mi][3] = *reinterpret_cast<const uint32_t*>(ba + G_MAT + 8 * G_STRIDE + co1);
            }
            uint32_t bh[8][2], bl[8][2];
            #pragma unroll
            for (int ni = 0; ni < 8; ni++) {
                const char* bb = st + 2 * G_MAT + (warpN + (ni << 3) + grp) * G_STRIDE;
                int co0 = (kb + (tig << 1)) << 1;
                int co1 = (kb + (tig << 1) + 8) << 1;
                bh[ni][0] = *reinterpret_cast<const uint32_t*>(bb + co0);
                bh[ni][1] = *reinterpret_cast<const uint32_t*>(bb + co1);
                bl[ni][0] = *reinterpret_cast<const uint32_t*>(bb + G_MAT + co0);
                bl[ni][1] = *reinterpret_cast<const uint32_t*>(bb + G_MAT + co1);
            }
            #pragma unroll
            for (int mi = 0; mi < 2; mi++)
                #pragma unroll
                for (int ni = 0; ni < 8; ni++) {
                    mma16816(acc[mi][ni], ah[mi], bh[ni]);
                    mma16816(acc[mi][ni], ah[mi], bl[ni]);
                    mma16816(acc[mi][ni], al[mi], bh[ni]);
                }
        }
    };

    // ---- pipelined main loop ----
    ldg(0); sts(0);
    if (nc > 1) ldg(1);
    for (int c = 0; c < nc; c++) {
        __syncthreads();
        compute(c & 1);
        if (c + 1 < nc) {
            sts((c + 1) & 1);
            if (c + 2 < nc) ldg(c + 2);
        }
    }

    // ---- epilogue ----
    #pragma unroll
    for (int mi = 0; mi < 2; mi++) {
        #pragma unroll
        for (int ni = 0; ni < 8; ni++) {
            int m = m0 + warpM + (mi << 4) + grp;
            int n = n0 + warpN + (ni << 3) + (tig << 1);
            float2 v0, v1;
            v0.x = acc[mi][ni][0]; v0.y = acc[mi][ni][1];
            v1.x = acc[mi][ni][2]; v1.y = acc[mi][ni][3];
            if (EPI == 1) {
                float b0 = bias[n], b1 = bias[n + 1];
                v0.x = geluf(v0.x + b0); v0.y = geluf(v0.y + b1);
                v1.x = geluf(v1.x + b0); v1.y = geluf(v1.y + b1);
            }
            *reinterpret_cast<float2*>(Cm + (size_t)m * N + n) = v0;
            *reinterpret_cast<float2*>(Cm + (size_t)(m + 8) * N + n) = v1;
        }
    }
}

// ---------------- streams: P -> gelu -> LN -> x_aug (warp-per-stream) ----------------
__global__ __launch_bounds__(96) void streams_kernel(
    const float* __restrict__ cls_b, const float* __restrict__ delta_b,
    const float* __restrict__ acc_b,
    const float* __restrict__ cg, const float* __restrict__ cbb,
    const float* __restrict__ dg, const float* __restrict__ dbb,
    const float* __restrict__ ag, const float* __restrict__ abb) {
    int row = blockIdx.x;
    int t = row % Tt;
    int w = threadIdx.x >> 5;     // stream 0..2
    int l = threadIdx.x & 31;
    const float* Pr = g_P + (size_t)row * AUGq;
    float* vr = g_v + (size_t)row * AUGq;
    const float* bsrc = (w == 0) ? cls_b : (w == 1) ? delta_b : acc_b;

    float act[4];
    #pragma unroll
    for (int q = 0; q < 4; q++) {
        int j = l + (q << 5);
        float p;
        if (w == 0) {
            p = Pr[j];
        } else if (w == 1) {
            int o = BDq + j;
            p = (t == 0) ? (Pr[o] - Pr[AUGq + o]) : (Pr[o] - Pr[o - AUGq]);
        } else {
            int o = 2 * BDq + j;
            if (t == 0)      p = Pr[o] - 2.0f * Pr[AUGq + o] + Pr[2 * AUGq + o];
            else if (t == 1) p = 2.0f * Pr[o] - 2.0f * Pr[o - AUGq];
            else             p = Pr[o] - 2.0f * Pr[o - AUGq] + Pr[o - 2 * AUGq];
        }
        act[q] = geluf(p + bsrc[j]);
    }
    float s = act[0] + act[1] + act[2] + act[3];
    #pragma unroll
    for (int o = 16; o > 0; o >>= 1) s += __shfl_xor_sync(0xffffffffu, s, o);
    float mu = s * (1.0f / 128.0f);
    float d0 = act[0] - mu, d1 = act[1] - mu, d2 = act[2] - mu, d3 = act[3] - mu;
    float vsum = d0 * d0 + d1 * d1 + d2 * d2 + d3 * d3;
    #pragma unroll
    for (int o = 16; o > 0; o >>= 1) vsum += __shfl_xor_sync(0xffffffffu, vsum, o);
    float rs = rsqrtf(vsum * (1.0f / 128.0f) + 1e-5f);
    const float* gsrc = (w == 0) ? cg : (w == 1) ? dg : ag;
    const float* b2   = (w == 0) ? cbb : (w == 1) ? dbb : abb;
    float dd[4] = {d0, d1, d2, d3};
    #pragma unroll
    for (int q = 0; q < 4; q++) {
        int j = l + (q << 5);
        vr[(w << 7) + j] = dd[q] * rs * gsrc[j] + b2[j];
    }
}

// ---------------- time-mean of u ----------------
__global__ void ubar_kernel() {
    int idx = blockIdx.x * blockDim.x + threadIdx.x;
    if (idx >= Bq * NUq) return;
    int b = idx / NUq, n = idx % NUq;
    const float* up = g_u + (size_t)b * Tt * NUq + n;
    float s = 0.0f;
    #pragma unroll
    for (int t = 0; t < Tt; t++) s += up[(size_t)t * NUq];
    g_ubar[idx] = s * (1.0f / 31.0f);
}

// ---------------- BiLSTM (batch-parallel recurrence) ----------------
#define RPB 8
__global__ __launch_bounds__(256) void lstm_kernel(const float* __restrict__ whh_f,
                                                   const float* __restrict__ b_f,
                                                   const float* __restrict__ whh_r,
                                                   const float* __restrict__ b_r) {
    const int dir = blockIdx.y;               // 0 fwd, 1 bwd
    const int b0 = blockIdx.x * RPB;
    const int j = threadIdx.x;                // gate column 0..255
    const float* whh  = dir ? whh_r : whh_f;
    const float* bias = dir ? b_r : b_f;
    const int off = dir ? 256 : 0;
    float* winbuf = dir ? g_winb : g_winf;

    float wcol[64];
    #pragma unroll
    for (int kk = 0; kk < 64; kk++) wcol[kk] = whh[kk * 256 + j];
    float base[RPB];
    #pragma unroll
    for (int r = 0; r < RPB; r++)
        base[r] = bias[j] - g_gbar[(size_t)(b0 + r) * NGq + off + j];

    __shared__ float hs[RPB][64];
    __shared__ float gs[RPB][256];
    if (j < 64) {
        #pragma unroll
        for (int r = 0; r < RPB; r++) hs[r][j] = 0.0f;
    }
    float creg[RPB];
    #pragma unroll
    for (int r = 0; r < RPB; r++) creg[r] = 0.0f;
    __syncthreads();

    for (int s = 0; s < Tt; s++) {
        int t = dir ? (Tt - 1 - s) : s;
        #pragma unroll
        for (int r = 0; r < RPB; r++) {
            float g = base[r] + g_G[((size_t)(b0 + r) * Tt + t) * NGq + off + j];
            #pragma unroll
            for (int kk = 0; kk < 64; kk += 4) {
                float4 h4 = *reinterpret_cast<const float4*>(&hs[r][kk]);
                g += wcol[kk] * h4.x + wcol[kk + 1] * h4.y
                   + wcol[kk + 2] * h4.z + wcol[kk + 3] * h4.w;
            }
            gs[r][j] = g;
        }
        __syncthreads();
        if (j < 64) {
            #pragma unroll
            for (int r = 0; r < RPB; r++) {
                float ig = sigf(gs[r][j]);
                float fg = sigf(gs[r][64 + j]);
                float gg = tanhf(gs[r][128 + j]);
                float og = sigf(gs[r][192 + j]);
                float c = fg * creg[r] + ig * gg;
                creg[r] = c;
                float h = og * tanhf(c);
                hs[r][j] = h;
                if (s >= 10 && s <= 20) {
                    int wt = dir ? (20 - s) : (s - 10);
                    winbuf[((size_t)(b0 + r) * TWq + wt) * HHq + j] = h;
                }
            }
        }
        __syncthreads();
    }
}

// ---------------- linear logits (xbar @ lin1_w + b) ----------------
__global__ void linlog_kernel(const float* __restrict__ w, const float* __restrict__ bb) {
    int idx = blockIdx.x * blockDim.x + threadIdx.x;
    if (idx >= Bq * OOq) return;
    int b = idx / OOq, o = idx % OOq;
    const float* xb = g_xbar + (size_t)b * Cc;
    float s = bb[o];
    #pragma unroll 8
    for (int c = 0; c < Cc; c++) s += xb[c] * w[c * OOq + o];
    g_linlog[idx] = s;
}

// ---------------- attention + final gate ----------------
__global__ __launch_bounds__(128) void attn_final_kernel(
    const float* __restrict__ attn_w, const float* __restrict__ attn_b,
    const float* __restrict__ attn_temp, const float* __restrict__ lin2_w,
    const float* __restrict__ lin2_b, const float* __restrict__ gate,
    float* __restrict__ out) {
    __shared__ float red[4];
    __shared__ float att[128];
    int b = blockIdx.x, k = threadIdx.x;
    float win[TWq];
    const float* src = (k < HHq) ? (g_winf + (size_t)b * TWq * HHq + k)
                                 : (g_winb + (size_t)b * TWq * HHq + (k - HHq));
    #pragma unroll
    for (int t = 0; t < TWq; t++) win[t] = src[t * HHq];

    float aw = attn_w[k];
    float ab = attn_b[0];
    float temp = log1pf(expf(attn_temp[0])) + 0.001f;
    float sc[TWq];
    #pragma unroll
    for (int t = 0; t < TWq; t++)
        sc[t] = (blksum128(win[t] * aw, red) + ab) / temp;

    float mx = sc[0];
    #pragma unroll
    for (int t = 1; t < TWq; t++) mx = fmaxf(mx, sc[t]);
    float den = 0.0f;
    #pragma unroll
    for (int t = 0; t < TWq; t++) { sc[t] = expf(sc[t] - mx); den += sc[t]; }
    float inv = 1.0f / den;
    float at = 0.0f;
    #pragma unroll
    for (int t = 0; t < TWq; t++) at += sc[t] * inv * win[t];

    out[(size_t)Bq * OOq + (size_t)b * 128 + k] = at;   // attended
    att[k] = at;
    __syncthreads();
    if (k < OOq) {
        float s = lin2_b[k];
        #pragma unroll 8
        for (int kk = 0; kk < 128; kk++) s += att[kk] * lin2_w[kk * OOq + k];
        float lin = g_linlog[b * OOq + k];
        float gg = 1.0f / (1.0f + expf(-gate[0]));
        out[b * OOq + k] = lin + gg * (s - lin);        // final_logits
    }
}

// ---------------- launch ----------------
extern "C" void kernel_launch(void* const* d_in, const int* in_sizes, int n_in,
                              void* d_out, int out_size) {
    const float* x        = (const float*)d_in[0];
    const float* cls_w    = (const float*)d_in[1];
    const float* cls_b    = (const float*)d_in[2];
    const float* delta_w  = (const float*)d_in[3];
    const float* delta_b  = (const float*)d_in[4];
    const float* acc_w    = (const float*)d_in[5];
    const float* acc_b    = (const float*)d_in[6];
    const float* cls_ln_g = (const float*)d_in[7];
    const float* cls_ln_b = (const float*)d_in[8];
    const float* delta_ln_g = (const float*)d_in[9];
    const float* delta_ln_b = (const float*)d_in[10];
    const float* acc_ln_g = (const float*)d_in[11];
    const float* acc_ln_b = (const float*)d_in[12];
    const float* lin0_w   = (const float*)d_in[13];
    const float* lin0_b   = (const float*)d_in[14];
    const float* gate     = (const float*)d_in[15];
    const float* attn_w   = (const float*)d_in[16];
    const float* attn_b   = (const float*)d_in[17];
    const float* attn_temp= (const float*)d_in[18];
    const float* lin1_w   = (const float*)d_in[19];
    const float* lin1_b   = (const float*)d_in[20];
    const float* lin2_w   = (const float*)d_in[21];
    const float* lin2_b   = (const float*)d_in[22];
    const float* wih_f    = (const float*)d_in[23];
    const float* whh_f    = (const float*)d_in[24];
    const float* b_f      = (const float*)d_in[25];
    const float* wih_r    = (const float*)d_in[26];
    const float* whh_r    = (const float*)d_in[27];
    const float* b_r      = (const float*)d_in[28];
    float* out = (float*)d_out;

    float *p_xs, *p_P, *p_v, *p_u, *p_ubar, *p_G, *p_gbar;
    __nv_bfloat16 *p_W3h, *p_W3l, *p_L0h, *p_L0l, *p_Wh, *p_Wl;
    cudaGetSymbolAddress((void**)&p_xs,   g_xs);
    cudaGetSymbolAddress((void**)&p_P,    g_P);
    cudaGetSymbolAddress((void**)&p_v,    g_v);
    cudaGetSymbolAddress((void**)&p_u,    g_u);
    cudaGetSymbolAddress((void**)&p_ubar, g_ubar);
    cudaGetSymbolAddress((void**)&p_G,    g_G);
    cudaGetSymbolAddress((void**)&p_gbar, g_gbar);
    cudaGetSymbolAddress((void**)&p_W3h,  g_W3t_hi);
    cudaGetSymbolAddress((void**)&p_W3l,  g_W3t_lo);
    cudaGetSymbolAddress((void**)&p_L0h,  g_L0t_hi);
    cudaGetSymbolAddress((void**)&p_L0l,  g_L0t_lo);
    cudaGetSymbolAddress((void**)&p_Wh,   g_Wt_hi);
    cudaGetSymbolAddress((void**)&p_Wl,   g_Wt_lo);

    cudaFuncSetAttribute(gemm_hmma<0>, cudaFuncAttributeMaxDynamicSharedMemorySize, G_SMEM);
    cudaFuncSetAttribute(gemm_hmma<1>, cudaFuncAttributeMaxDynamicSharedMemorySize, G_SMEM);

    // 1. convert/pack weights to bf16 hi/lo transposed
    convert_b_kernel<<<(AUGq * Cc + 255) / 256, 256>>>(cls_w, delta_w, acc_w, lin0_w, wih_f, wih_r);
    // 2. EMA scan + window mean
    ema_kernel<<<(Bq * Cc + 255) / 256, 256>>>(x);
    // 3. P = xs @ W3   (126976 x 768 -> 384)
    gemm_hmma<0><<<dim3(AUGq / 128, BTq / 128), 256, G_SMEM>>>(p_xs, p_W3h, p_W3l, p_P, BTq, AUGq, Cc, nullptr);
    // 4. streams -> gelu -> LN -> x_aug
    streams_kernel<<<BTq, 96>>>(cls_b, delta_b, acc_b,
                                cls_ln_g, cls_ln_b, delta_ln_g, delta_ln_b,
                                acc_ln_g, acc_ln_b);
    // 5. u = gelu(v @ lin0_w + b)   (126976 x 384 -> 256)
    gemm_hmma<1><<<dim3(NUq / 128, BTq / 128), 256, G_SMEM>>>(p_v, p_L0h, p_L0l, p_u, BTq, NUq, AUGq, lin0_b);
    // 6. ubar = mean_t(u)
    ubar_kernel<<<(Bq * NUq + 255) / 256, 256>>>();
    // 7. G = u @ Wih   (126976 x 256 -> 512)
    gemm_hmma<0><<<dim3(NGq / 128, BTq / 128), 256, G_SMEM>>>(p_u, p_Wh, p_Wl, p_G, BTq, NGq, NUq, nullptr);
    // 8. gbar = ubar @ Wih   (4096 x 256 -> 512)
    gemm_hmma<0><<<dim3(NGq / 128, Bq / 128), 256, G_SMEM>>>(p_ubar, p_Wh, p_Wl, p_gbar, Bq, NGq, NUq, nullptr);
    // 9. BiLSTM recurrence
    lstm_kernel<<<dim3(Bq / RPB, 2), 256>>>(whh_f, b_f, whh_r, b_r);
    // 10. linear logits
    linlog_kernel<<<(Bq * OOq + 255) / 256, 256>>>(lin1_w, lin1_b);
    // 11. attention + final mix -> out
    attn_final_kernel<<<Bq, 128>>>(attn_w, attn_b, attn_temp, lin2_w, lin2_b, gate, out);
}

// round 8
// speedup vs baseline: 2.5075x; 1.4229x over previous
#include <cuda_runtime.h>
#include <cuda_fp16.h>
#include <math.h>
#include <stdint.h>

// ---------------- problem dims ----------------
#define Bq   4096
#define Tt   31
#define Cc   768
#define BDq  128
#define AUGq 384
#define NUq  256     // lin0 out
#define HHq  64      // lstm hidden
#define NGq  512     // gates both directions (4H * 2)
#define OOq  12
#define TWq  11      // attention window length (t in [10,21))
#define BTq  (Bq*Tt) // 126976

// ---------------- device scratch (no allocations allowed) ----------------
static __device__ __half g_xs_h[(size_t)Bq*Tt*Cc];   // x_smooth (fp16, GEMM1 A)
static __device__ float  g_xbar[(size_t)Bq*Cc];      // window mean of x_smooth (fp32, exact path)
static __device__ float  g_P   [(size_t)Bq*Tt*AUGq]; // xs @ [cls|delta|acc] (fp32)
static __device__ __half g_v_h [(size_t)Bq*Tt*AUGq]; // x_aug (fp16, GEMM2 A)
static __device__ __half g_u_h [(size_t)Bq*Tt*NUq];  // gelu(lin0) (fp16, GEMM3 A)
static __device__ __half g_ubar_h[(size_t)Bq*NUq];   // time-mean of u (fp16)
static __device__ float  g_G   [(size_t)Bq*Tt*NGq];  // u @ [wih_f|wih_r] (fp32)
static __device__ float  g_gbar[(size_t)Bq*NGq];     // ubar @ [wih_f|wih_r] (fp32)
static __device__ float  g_winf[(size_t)Bq*TWq*HHq];
static __device__ float  g_winb[(size_t)Bq*TWq*HHq];
static __device__ float  g_linlog[(size_t)Bq*OOq];

// fp16 weight matrices, stored [N][K] (K-major, i.e. transposed)
static __device__ __half g_W3t[(size_t)AUGq*Cc];
static __device__ __half g_L0t[(size_t)NUq*AUGq];
static __device__ __half g_Wt [(size_t)NGq*NUq];

// ---------------- generic helpers ----------------
__device__ __forceinline__ float geluf(float x) {
    return 0.5f * x * (1.0f + erff(x * 0.7071067811865476f));
}
__device__ __forceinline__ float sigf(float x) { return 1.0f / (1.0f + expf(-x)); }

__device__ __forceinline__ float blksum128(float v, volatile float* sw) {
    #pragma unroll
    for (int o = 16; o > 0; o >>= 1) v += __shfl_down_sync(0xffffffffu, v, o);
    int lane = threadIdx.x & 31, w = threadIdx.x >> 5;
    __syncthreads();
    if (lane == 0) sw[w] = v;
    __syncthreads();
    return sw[0] + sw[1] + sw[2] + sw[3];
}

// mma.sync m16n8k16 fp16 -> f32 accumulate (HMMA path; target-generic PTX)
__device__ __forceinline__ void mma16816(float* c, const uint32_t* a, const uint32_t* b) {
    asm volatile(
        "mma.sync.aligned.m16n8k16.row.col.f32.f16.f16.f32 "
        "{%0,%1,%2,%3}, {%4,%5,%6,%7}, {%8,%9}, {%0,%1,%2,%3};"
        : "+f"(c[0]), "+f"(c[1]), "+f"(c[2]), "+f"(c[3])
        : "r"(a[0]), "r"(a[1]), "r"(a[2]), "r"(a[3]), "r"(b[0]), "r"(b[1]));
}

// ---------------- weight convert: pack + transpose -> fp16 ----------------
__global__ void convert_b_kernel(const float* __restrict__ cls_w, const float* __restrict__ delta_w,
                                 const float* __restrict__ acc_w, const float* __restrict__ lin0_w,
                                 const float* __restrict__ wih_f, const float* __restrict__ wih_r) {
    int idx = blockIdx.x * blockDim.x + threadIdx.x;
    if (idx < AUGq * Cc) {
        int n = idx / Cc, c = idx % Cc;
        float w = (n < BDq) ? cls_w[c * BDq + n]
                : (n < 2 * BDq) ? delta_w[c * BDq + (n - BDq)]
                : acc_w[c * BDq + (n - 2 * BDq)];
        g_W3t[idx] = __float2half(w);
    }
    if (idx < NUq * AUGq) {
        int n = idx / AUGq, c = idx % AUGq;
        g_L0t[idx] = __float2half(lin0_w[c * NUq + n]);
    }
    if (idx < NGq * NUq) {
        int n = idx >> 8, c = idx & 255;
        float w = (n < 256) ? wih_f[c * 256 + n] : wih_r[c * 256 + (n - 256)];
        g_Wt[idx] = __float2half(w);
    }
}

// ---------------- EMA scan + window mean ----------------
__global__ void ema_kernel(const float* __restrict__ x) {
    int idx = blockIdx.x * blockDim.x + threadIdx.x;
    if (idx >= Bq * Cc) return;
    int b = idx / Cc, c = idx % Cc;
    const float* xp = x + (size_t)b * Tt * Cc + c;
    __half* xsp = g_xs_h + (size_t)b * Tt * Cc + c;
    float s = xp[0];
    xsp[0] = __float2half(s);
    float wsum = 0.0f;
    #pragma unroll
    for (int t = 1; t < Tt; t++) {
        float xt = xp[(size_t)t * Cc];
        s = s + 0.3f * (xt - s);
        xsp[(size_t)t * Cc] = __float2half(s);
        if (t >= 10 && t < 21) wsum += s;
    }
    g_xbar[idx] = wsum * (1.0f / 11.0f);
}

// ---------------- HMMA GEMM: C[M,N] = A[M,K](fp16) @ Bt[N,K](fp16)^T -------------
// 128x128 block tile, BK=32, 8 warps (warp tile 32x64), double-buffered SMEM,
// register prefetch. 80B row stride (40 halves) -> conflict-free LDS + aligned STS.128.
// EPI==0: raw fp32 store. EPI==1: fp16 store of gelu(acc + bias[n]).
#define H_STRIDE 80                   // bytes per smem row
#define H_MAT    (128 * H_STRIDE)     // 10240 bytes per matrix
#define H_STAGE  (2 * H_MAT)          // A + B
#define H_SMEM   (2 * H_STAGE)        // 40960 bytes (double buffered)

template<int EPI, typename OutT>
__global__ __launch_bounds__(256, 1)
void gemm_h(const __half* __restrict__ A, const __half* __restrict__ Bt,
            OutT* __restrict__ Cm, int M, int N, int K, const float* __restrict__ bias) {
    extern __shared__ char smem[];
    const int tid = threadIdx.x, wid = tid >> 5, lane = tid & 31;
    const int grp = lane >> 2, tig = lane & 3;
    const int m0 = blockIdx.y << 7, n0 = blockIdx.x << 7;
    const int warpM = (wid >> 1) << 5, warpN = (wid & 1) << 6;

    float acc[2][8][4];
    #pragma unroll
    for (int mi = 0; mi < 2; mi++)
        #pragma unroll
        for (int ni = 0; ni < 8; ni++)
            #pragma unroll
            for (int q = 0; q < 4; q++) acc[mi][ni][q] = 0.0f;

    const int nc = K >> 5;
    uint4 av[2], bv[2];

    // load chunk c into registers (A and B tiles are 128 rows x 32 halves)
    auto ldg = [&](int c) {
        const int k0 = c << 5;
        #pragma unroll
        for (int i = 0; i < 2; i++) {
            int id = (i << 8) + tid;            // 0..511
            int r = id >> 2, c16 = id & 3;      // 4 x uint4 (8 halves) per row
            av[i] = *reinterpret_cast<const uint4*>(A + (size_t)(m0 + r) * K + k0 + (c16 << 3));
            bv[i] = *reinterpret_cast<const uint4*>(Bt + (size_t)(n0 + r) * K + k0 + (c16 << 3));
        }
    };
    auto sts = [&](int s) {
        char* st = smem + s * H_STAGE;
        #pragma unroll
        for (int i = 0; i < 2; i++) {
            int id = (i << 8) + tid;
            int r = id >> 2, c16 = id & 3;
            *reinterpret_cast<uint4*>(st + r * H_STRIDE + (c16 << 4)) = av[i];
            *reinterpret_cast<uint4*>(st + H_MAT + r * H_STRIDE + (c16 << 4)) = bv[i];
        }
    };
    auto compute = [&](int s) {
        const char* st = smem + s * H_STAGE;
        #pragma unroll
        for (int ks = 0; ks < 2; ks++) {
            const int kb = ks << 4;
            const int co0 = (kb + (tig << 1)) << 1;
            const int co1 = co0 + 16;
            uint32_t a[2][4];
            #pragma unroll
            for (int mi = 0; mi < 2; mi++) {
                const char* ba = st + (warpM + (mi << 4) + grp) * H_STRIDE;
                a[mi][0] = *reinterpret_cast<const uint32_t*>(ba + co0);
                a[mi][1] = *reinterpret_cast<const uint32_t*>(ba + 8 * H_STRIDE + co0);
                a[mi][2] = *reinterpret_cast<const uint32_t*>(ba + co1);
                a[mi][3] = *reinterpret_cast<const uint32_t*>(ba + 8 * H_STRIDE + co1);
            }
            uint32_t b[8][2];
            #pragma unroll
            for (int ni = 0; ni < 8; ni++) {
                const char* bb = st + H_MAT + (warpN + (ni << 3) + grp) * H_STRIDE;
                b[ni][0] = *reinterpret_cast<const uint32_t*>(bb + co0);
                b[ni][1] = *reinterpret_cast<const uint32_t*>(bb + co1);
            }
            #pragma unroll
            for (int mi = 0; mi < 2; mi++)
                #pragma unroll
                for (int ni = 0; ni < 8; ni++)
                    mma16816(acc[mi][ni], a[mi], b[ni]);
        }
    };

    ldg(0); sts(0);
    if (nc > 1) ldg(1);
    for (int c = 0; c < nc; c++) {
        __syncthreads();
        compute(c & 1);
        if (c + 1 < nc) {
            sts((c + 1) & 1);
            if (c + 2 < nc) ldg(c + 2);
        }
    }

    // epilogue
    #pragma unroll
    for (int mi = 0; mi < 2; mi++) {
        #pragma unroll
        for (int ni = 0; ni < 8; ni++) {
            int m = m0 + warpM + (mi << 4) + grp;
            int n = n0 + warpN + (ni << 3) + (tig << 1);
            float c0 = acc[mi][ni][0], c1 = acc[mi][ni][1];
            float c2 = acc[mi][ni][2], c3 = acc[mi][ni][3];
            if (EPI == 1) {
                float b0 = bias[n], b1 = bias[n + 1];
                c0 = geluf(c0 + b0); c1 = geluf(c1 + b1);
                c2 = geluf(c2 + b0); c3 = geluf(c3 + b1);
            }
            if (sizeof(OutT) == 2) {
                __half2* p0 = reinterpret_cast<__half2*>((__half*)Cm + (size_t)m * N + n);
                __half2* p1 = reinterpret_cast<__half2*>((__half*)Cm + (size_t)(m + 8) * N + n);
                *p0 = __floats2half2_rn(c0, c1);
                *p1 = __floats2half2_rn(c2, c3);
            } else {
                float2 v0; v0.x = c0; v0.y = c1;
                float2 v1; v1.x = c2; v1.y = c3;
                *reinterpret_cast<float2*>((float*)Cm + (size_t)m * N + n) = v0;
                *reinterpret_cast<float2*>((float*)Cm + (size_t)(m + 8) * N + n) = v1;
            }
        }
    }
}

// ---------------- streams: P -> gelu -> LN -> x_aug (warp-per-stream, fp16 out) -------
__global__ __launch_bounds__(96) void streams_kernel(
    const float* __restrict__ cls_b, const float* __restrict__ delta_b,
    const float* __restrict__ acc_b,
    const float* __restrict__ cg, const float* __restrict__ cbb,
    const float* __restrict__ dg, const float* __restrict__ dbb,
    const float* __restrict__ ag, const float* __restrict__ abb) {
    int row = blockIdx.x;
    int t = row % Tt;
    int w = threadIdx.x >> 5;     // stream 0..2
    int l = threadIdx.x & 31;
    const float* Pr = g_P + (size_t)row * AUGq;
    __half* vr = g_v_h + (size_t)row * AUGq;
    const float* bsrc = (w == 0) ? cls_b : (w == 1) ? delta_b : acc_b;

    float act[4];
    #pragma unroll
    for (int q = 0; q < 4; q++) {
        int j = l + (q << 5);
        float p;
        if (w == 0) {
            p = Pr[j];
        } else if (w == 1) {
            int o = BDq + j;
            p = (t == 0) ? (Pr[o] - Pr[AUGq + o]) : (Pr[o] - Pr[o - AUGq]);
        } else {
            int o = 2 * BDq + j;
            if (t == 0)      p = Pr[o] - 2.0f * Pr[AUGq + o] + Pr[2 * AUGq + o];
            else if (t == 1) p = 2.0f * Pr[o] - 2.0f * Pr[o - AUGq];
            else             p = Pr[o] - 2.0f * Pr[o - AUGq] + Pr[o - 2 * AUGq];
        }
        act[q] = geluf(p + bsrc[j]);
    }
    float s = act[0] + act[1] + act[2] + act[3];
    #pragma unroll
    for (int o = 16; o > 0; o >>= 1) s += __shfl_xor_sync(0xffffffffu, s, o);
    float mu = s * (1.0f / 128.0f);
    float d0 = act[0] - mu, d1 = act[1] - mu, d2 = act[2] - mu, d3 = act[3] - mu;
    float vsum = d0 * d0 + d1 * d1 + d2 * d2 + d3 * d3;
    #pragma unroll
    for (int o = 16; o > 0; o >>= 1) vsum += __shfl_xor_sync(0xffffffffu, vsum, o);
    float rs = rsqrtf(vsum * (1.0f / 128.0f) + 1e-5f);
    const float* gsrc = (w == 0) ? cg : (w == 1) ? dg : ag;
    const float* b2   = (w == 0) ? cbb : (w == 1) ? dbb : abb;
    float dd[4] = {d0, d1, d2, d3};
    #pragma unroll
    for (int q = 0; q < 4; q++) {
        int j = l + (q << 5);
        vr[(w << 7) + j] = __float2half(dd[q] * rs * gsrc[j] + b2[j]);
    }
}

// ---------------- time-mean of u ----------------
__global__ void ubar_kernel() {
    int idx = blockIdx.x * blockDim.x + threadIdx.x;
    if (idx >= Bq * NUq) return;
    int b = idx / NUq, n = idx % NUq;
    const __half* up = g_u_h + (size_t)b * Tt * NUq + n;
    float s = 0.0f;
    #pragma unroll
    for (int t = 0; t < Tt; t++) s += __half2float(up[(size_t)t * NUq]);
    g_ubar_h[idx] = __float2half(s * (1.0f / 31.0f));
}

// ---------------- BiLSTM (batch-parallel recurrence) ----------------
#define RPB 8
__global__ __launch_bounds__(256) void lstm_kernel(const float* __restrict__ whh_f,
                                                   const float* __restrict__ b_f,
                                                   const float* __restrict__ whh_r,
                                                   const float* __restrict__ b_r) {
    const int dir = blockIdx.y;               // 0 fwd, 1 bwd
    const int b0 = blockIdx.x * RPB;
    const int j = threadIdx.x;                // gate column 0..255
    const float* whh  = dir ? whh_r : whh_f;
    const float* bias = dir ? b_r : b_f;
    const int off = dir ? 256 : 0;
    float* winbuf = dir ? g_winb : g_winf;

    float wcol[64];
    #pragma unroll
    for (int kk = 0; kk < 64; kk++) wcol[kk] = whh[kk * 256 + j];
    float base[RPB];
    #pragma unroll
    for (int r = 0; r < RPB; r++)
        base[r] = bias[j] - g_gbar[(size_t)(b0 + r) * NGq + off + j];

    __shared__ float hs[RPB][64];
    __shared__ float gs[RPB][256];
    if (j < 64) {
        #pragma unroll
        for (int r = 0; r < RPB; r++) hs[r][j] = 0.0f;
    }
    float creg[RPB];
    #pragma unroll
    for (int r = 0; r < RPB; r++) creg[r] = 0.0f;
    __syncthreads();

    for (int s = 0; s < Tt; s++) {
        int t = dir ? (Tt - 1 - s) : s;
        #pragma unroll
        for (int r = 0; r < RPB; r++) {
            float g = base[r] + g_G[((size_t)(b0 + r) * Tt + t) * NGq + off + j];
            #pragma unroll
            for (int kk = 0; kk < 64; kk += 4) {
                float4 h4 = *reinterpret_cast<const float4*>(&hs[r][kk]);
                g += wcol[kk] * h4.x + wcol[kk + 1] * h4.y
                   + wcol[kk + 2] * h4.z + wcol[kk + 3] * h4.w;
            }
            gs[r][j] = g;
        }
        __syncthreads();
        if (j < 64) {
            #pragma unroll
            for (int r = 0; r < RPB; r++) {
                float ig = sigf(gs[r][j]);
                float fg = sigf(gs[r][64 + j]);
                float gg = tanhf(gs[r][128 + j]);
                float og = sigf(gs[r][192 + j]);
                float c = fg * creg[r] + ig * gg;
                creg[r] = c;
                float h = og * tanhf(c);
                hs[r][j] = h;
                if (s >= 10 && s <= 20) {
                    int wt = dir ? (20 - s) : (s - 10);
                    winbuf[((size_t)(b0 + r) * TWq + wt) * HHq + j] = h;
                }
            }
        }
        __syncthreads();
    }
}

// ---------------- linear logits (xbar @ lin1_w + b), exact fp32 ----------------
__global__ void linlog_kernel(const float* __restrict__ w, const float* __restrict__ bb) {
    int idx = blockIdx.x * blockDim.x + threadIdx.x;
    if (idx >= Bq * OOq) return;
    int b = idx / OOq, o = idx % OOq;
    const float* xb = g_xbar + (size_t)b * Cc;
    float s = bb[o];
    #pragma unroll 8
    for (int c = 0; c < Cc; c++) s += xb[c] * w[c * OOq + o];
    g_linlog[idx] = s;
}

// ---------------- attention + final gate ----------------
__global__ __launch_bounds__(128) void attn_final_kernel(
    const float* __restrict__ attn_w, const float* __restrict__ attn_b,
    const float* __restrict__ attn_temp, const float* __restrict__ lin2_w,
    const float* __restrict__ lin2_b, const float* __restrict__ gate,
    float* __restrict__ out) {
    __shared__ float red[4];
    __shared__ float att[128];
    int b = blockIdx.x, k = threadIdx.x;
    float win[TWq];
    const float* src = (k < HHq) ? (g_winf + (size_t)b * TWq * HHq + k)
                                 : (g_winb + (size_t)b * TWq * HHq + (k - HHq));
    #pragma unroll
    for (int t = 0; t < TWq; t++) win[t] = src[t * HHq];

    float aw = attn_w[k];
    float ab = attn_b[0];
    float temp = log1pf(expf(attn_temp[0])) + 0.001f;
    float sc[TWq];
    #pragma unroll
    for (int t = 0; t < TWq; t++)
        sc[t] = (blksum128(win[t] * aw, red) + ab) / temp;

    float mx = sc[0];
    #pragma unroll
    for (int t = 1; t < TWq; t++) mx = fmaxf(mx, sc[t]);
    float den = 0.0f;
    #pragma unroll
    for (int t = 0; t < TWq; t++) { sc[t] = expf(sc[t] - mx); den += sc[t]; }
    float inv = 1.0f / den;
    float at = 0.0f;
    #pragma unroll
    for (int t = 0; t < TWq; t++) at += sc[t] * inv * win[t];

    out[(size_t)Bq * OOq + (size_t)b * 128 + k] = at;   // attended
    att[k] = at;
    __syncthreads();
    if (k < OOq) {
        float s = lin2_b[k];
        #pragma unroll 8
        for (int kk = 0; kk < 128; kk++) s += att[kk] * lin2_w[kk * OOq + k];
        float lin = g_linlog[b * OOq + k];
        float gg = 1.0f / (1.0f + expf(-gate[0]));
        out[b * OOq + k] = lin + gg * (s - lin);        // final_logits
    }
}

// ---------------- launch ----------------
extern "C" void kernel_launch(void* const* d_in, const int* in_sizes, int n_in,
                              void* d_out, int out_size) {
    const float* x        = (const float*)d_in[0];
    const float* cls_w    = (const float*)d_in[1];
    const float* cls_b    = (const float*)d_in[2];
    const float* delta_w  = (const float*)d_in[3];
    const float* delta_b  = (const float*)d_in[4];
    const float* acc_w    = (const float*)d_in[5];
    const float* acc_b    = (const float*)d_in[6];
    const float* cls_ln_g = (const float*)d_in[7];
    const float* cls_ln_b = (const float*)d_in[8];
    const float* delta_ln_g = (const float*)d_in[9];
    const float* delta_ln_b = (const float*)d_in[10];
    const float* acc_ln_g = (const float*)d_in[11];
    const float* acc_ln_b = (const float*)d_in[12];
    const float* lin0_w   = (const float*)d_in[13];
    const float* lin0_b   = (const float*)d_in[14];
    const float* gate     = (const float*)d_in[15];
    const float* attn_w   = (const float*)d_in[16];
    const float* attn_b   = (const float*)d_in[17];
    const float* attn_temp= (const float*)d_in[18];
    const float* lin1_w   = (const float*)d_in[19];
    const float* lin1_b   = (const float*)d_in[20];
    const float* lin2_w   = (const float*)d_in[21];
    const float* lin2_b   = (const float*)d_in[22];
    const float* wih_f    = (const float*)d_in[23];
    const float* whh_f    = (const float*)d_in[24];
    const float* b_f      = (const float*)d_in[25];
    const float* wih_r    = (const float*)d_in[26];
    const float* whh_r    = (const float*)d_in[27];
    const float* b_r      = (const float*)d_in[28];
    float* out = (float*)d_out;

    __half *p_xs, *p_v, *p_u, *p_ubar, *p_W3, *p_L0, *p_W;
    float *p_P, *p_G, *p_gbar;
    cudaGetSymbolAddress((void**)&p_xs,   g_xs_h);
    cudaGetSymbolAddress((void**)&p_P,    g_P);
    cudaGetSymbolAddress((void**)&p_v,    g_v_h);
    cudaGetSymbolAddress((void**)&p_u,    g_u_h);
    cudaGetSymbolAddress((void**)&p_ubar, g_ubar_h);
    cudaGetSymbolAddress((void**)&p_G,    g_G);
    cudaGetSymbolAddress((void**)&p_gbar, g_gbar);
    cudaGetSymbolAddress((void**)&p_W3,   g_W3t);
    cudaGetSymbolAddress((void**)&p_L0,   g_L0t);
    cudaGetSymbolAddress((void**)&p_W,    g_Wt);

    cudaFuncSetAttribute(gemm_h<0, float>,  cudaFuncAttributeMaxDynamicSharedMemorySize, H_SMEM);
    cudaFuncSetAttribute(gemm_h<1, __half>, cudaFuncAttributeMaxDynamicSharedMemorySize, H_SMEM);

    // 1. convert/pack weights to fp16 transposed
    convert_b_kernel<<<(AUGq * Cc + 255) / 256, 256>>>(cls_w, delta_w, acc_w, lin0_w, wih_f, wih_r);
    // 2. EMA scan + window mean (xs stored fp16)
    ema_kernel<<<(Bq * Cc + 255) / 256, 256>>>(x);
    // 3. P = xs @ W3   (126976 x 768 -> 384), fp32 out
    gemm_h<0, float><<<dim3(AUGq / 128, BTq / 128), 256, H_SMEM>>>(p_xs, p_W3, p_P, BTq, AUGq, Cc, nullptr);
    // 4. streams -> gelu -> LN -> x_aug (fp16 out)
    streams_kernel<<<BTq, 96>>>(cls_b, delta_b, acc_b,
                                cls_ln_g, cls_ln_b, delta_ln_g, delta_ln_b,
                                acc_ln_g, acc_ln_b);
    // 5. u = gelu(v @ lin0_w + b)   (126976 x 384 -> 256), fp16 out
    gemm_h<1, __half><<<dim3(NUq / 128, BTq / 128), 256, H_SMEM>>>(p_v, p_L0, p_u, BTq, NUq, AUGq, lin0_b);
    // 6. ubar = mean_t(u) (fp16)
    ubar_kernel<<<(Bq * NUq + 255) / 256, 256>>>();
    // 7. G = u @ Wih   (126976 x 256 -> 512), fp32 out
    gemm_h<0, float><<<dim3(NGq / 128, BTq / 128), 256, H_SMEM>>>(p_u, p_W, p_G, BTq, NGq, NUq, nullptr);
    // 8. gbar = ubar @ Wih   (4096 x 256 -> 512), fp32 out
    gemm_h<0, float><<<dim3(NGq / 128, Bq / 128), 256, H_SMEM>>>(p_ubar, p_W, p_gbar, Bq, NGq, NUq, nullptr);
    // 9. BiLSTM recurrence
    lstm_kernel<<<dim3(Bq / RPB, 2), 256>>>(whh_f, b_f, whh_r, b_r);
    // 10. linear logits (exact fp32 path)
    linlog_kernel<<<(Bq * OOq + 255) / 256, 256>>>(lin1_w, lin1_b);
    // 11. attention + final mix -> out
    attn_final_kernel<<<Bq, 128>>>(attn_w, attn_b, attn_temp, lin2_w, lin2_b, gate, out);
}